// round 10
// baseline (speedup 1.0000x reference)
#include <cuda_runtime.h>
#include <cstdint>
#include <cstddef>

// out[t,e,o] = sum_r x[t, e*128+r] * W[e,o,r]
// x: [8192, 1024] f32, W: [8, 4096, 128] f32, out: [8192, 8, 4096] f32
//
// mma.sync TF32 (tcgen05 unavailable: harness compiles via compute_103 PTX).
// Round 10 = Round 8 structure with 512 threads (16 warps, warp tile 32x64,
// 4 warps/SMSP for latency hiding). Operands pre-rounded to TF32 in scratch;
// tiles loaded via cp.async.cg in a 2-stage k-pipeline (k[0:64] / k[64:128]).
// LDS.64 k-slot-permutation fragments: MMA k-slots (tig, tig+4) of k-step j
// read physical k = {8j+2tig, 8j+2tig+1} (contiguous pair, conflict-free
// under swizzle col ^= 8*(row&7)).

#define EXPERTS 8
#define RANK    128
#define OUTF    4096
#define TOKENS  8192
#define BM      128
#define BN      256
#define NTHREADS 512

#define SM_X 0
#define SM_W 65536
#define SMEM_TOTAL (65536 + 131072)   // 192KB

__device__ float g_Xr[(size_t)TOKENS * EXPERTS * RANK];   // 32MB tf32-rounded x
__device__ float g_Wr[(size_t)EXPERTS * OUTF * RANK];     // 16MB tf32-rounded W

__device__ __forceinline__ uint32_t tf32u(float f) {
    uint32_t u;
    asm("cvt.rna.tf32.f32 %0, %1;" : "=r"(u) : "f"(f));
    return u;
}
__device__ __forceinline__ uint32_t smem_u32(const void* p) {
    uint32_t a;
    asm("{ .reg .u64 t; cvta.to.shared.u64 t, %1; cvt.u32.u64 %0, t; }" : "=r"(a) : "l"(p));
    return a;
}
__device__ __forceinline__ void cp16(uint32_t dst, const void* src) {
    asm volatile("cp.async.cg.shared.global [%0], [%1], 16;" :: "r"(dst), "l"(src) : "memory");
}
__device__ __forceinline__ void mma_tf32(float c[4],
                                         uint32_t a0, uint32_t a1, uint32_t a2, uint32_t a3,
                                         uint32_t b0, uint32_t b1) {
    asm volatile(
        "mma.sync.aligned.m16n8k8.row.col.f32.tf32.tf32.f32 "
        "{%0,%1,%2,%3}, {%4,%5,%6,%7}, {%8,%9}, {%0,%1,%2,%3};"
        : "+f"(c[0]), "+f"(c[1]), "+f"(c[2]), "+f"(c[3])
        : "r"(a0), "r"(a1), "r"(a2), "r"(a3), "r"(b0), "r"(b1));
}

// ---- streaming pre-round kernels ----
__global__ void __launch_bounds__(1024, 2) round_x(const float4* __restrict__ src, int n4) {
    int i = blockIdx.x * blockDim.x + threadIdx.x;
    if (i < n4) {
        float4 v = src[i];
        reinterpret_cast<uint4*>(g_Xr)[i] =
            make_uint4(tf32u(v.x), tf32u(v.y), tf32u(v.z), tf32u(v.w));
    }
}
__global__ void __launch_bounds__(1024, 2) round_w(const float4* __restrict__ src, int n4) {
    int i = blockIdx.x * blockDim.x + threadIdx.x;
    if (i < n4) {
        float4 v = src[i];
        reinterpret_cast<uint4*>(g_Wr)[i] =
            make_uint4(tf32u(v.x), tf32u(v.y), tf32u(v.z), tf32u(v.w));
    }
}

extern "C" __global__ void __launch_bounds__(NTHREADS, 1)
moelb_v7(float* __restrict__ out)
{
    extern __shared__ char smem[];
    const uint32_t sb = smem_u32(smem);
    float* Xs = reinterpret_cast<float*>(smem + SM_X);   // [128][128] swizzled
    float* Ws = reinterpret_cast<float*>(smem + SM_W);   // [256][128] swizzled

    const int tid  = threadIdx.x;
    const int wid  = tid >> 5;
    const int lane = tid & 31;
    const int g    = lane >> 2;
    const int tig  = lane & 3;

    const int tOff = blockIdx.x * BM;
    const int nOff = blockIdx.y * BN;
    const int e    = blockIdx.z;

    // ---- issue both k-stages with cp.async (stage s covers float4 slots q = s*16..s*16+15) ----
    const float* xsrc = g_Xr + (size_t)tOff * (EXPERTS * RANK) + e * RANK;
    const float* wsrc = g_Wr + ((size_t)e * OUTF + nOff) * RANK;

    #pragma unroll
    for (int s = 0; s < 2; ++s) {
        #pragma unroll
        for (int p = 0; p < 4; ++p) {                     // X: 128 rows x 16 q
            int idx = p * NTHREADS + tid;
            int row = idx >> 4, q = s * 16 + (idx & 15);
            uint32_t dst = sb + SM_X + (uint32_t)row * 512
                         + (((uint32_t)q * 16) ^ (((uint32_t)row & 7) << 5));
            cp16(dst, xsrc + (size_t)row * (EXPERTS * RANK) + q * 4);
        }
        #pragma unroll
        for (int p = 0; p < 8; ++p) {                     // W: 256 rows x 16 q
            int idx = p * NTHREADS + tid;
            int row = idx >> 4, q = s * 16 + (idx & 15);
            uint32_t dst = sb + SM_W + (uint32_t)row * 512
                         + (((uint32_t)q * 16) ^ (((uint32_t)row & 7) << 5));
            cp16(dst, wsrc + (size_t)row * RANK + q * 4);
        }
        asm volatile("cp.async.commit_group;" ::: "memory");
    }

    // ---- warp mapping: 16 warps = 4(M) x 4(N), warp tile 32x64 ----
    const int mW  = (wid >> 2) * 32;       // 0,32,64,96
    const int nW  = (wid & 3) * 64;        // 0,64,128,192
    const int skf = g << 3;
    const int t2  = tig << 1;

    int aRow[2][2], bRow[8];
    #pragma unroll
    for (int mt = 0; mt < 2; ++mt) {
        aRow[mt][0] = (mW + mt * 16 + g) * RANK;
        aRow[mt][1] = (mW + mt * 16 + 8 + g) * RANK;
    }
    #pragma unroll
    for (int nt = 0; nt < 8; ++nt)
        bRow[nt] = (nW + nt * 8 + g) * RANK;

    float acc[2][8][4];
    #pragma unroll
    for (int mt = 0; mt < 2; ++mt)
        #pragma unroll
        for (int nt = 0; nt < 8; ++nt)
            #pragma unroll
            for (int i = 0; i < 4; ++i)
                acc[mt][nt][i] = 0.0f;

    float2 Af[2][2][2];   // A double-buffered
    float2 Bf[8];         // B single-buffered (warp interleave hides LDS latency)

    #pragma unroll
    for (int half = 0; half < 2; ++half) {
        if (half == 0) asm volatile("cp.async.wait_group 1;" ::: "memory");
        else           asm volatile("cp.async.wait_group 0;" ::: "memory");
        __syncthreads();

        // prologue: A fragments for first k-step of this half
        {
            const int o = (((half * 8) << 3) ^ skf) + t2;
            #pragma unroll
            for (int mt = 0; mt < 2; ++mt) {
                Af[0][mt][0] = *reinterpret_cast<const float2*>(&Xs[aRow[mt][0] + o]);
                Af[0][mt][1] = *reinterpret_cast<const float2*>(&Xs[aRow[mt][1] + o]);
            }
        }

        #pragma unroll
        for (int jj = 0; jj < 8; ++jj) {
            const int s = jj & 1;
            const int o = (((half * 8 + jj) << 3) ^ skf) + t2;
            if (jj < 7) {
                const int on = (((half * 8 + jj + 1) << 3) ^ skf) + t2;
                const int n = s ^ 1;
                #pragma unroll
                for (int mt = 0; mt < 2; ++mt) {
                    Af[n][mt][0] = *reinterpret_cast<const float2*>(&Xs[aRow[mt][0] + on]);
                    Af[n][mt][1] = *reinterpret_cast<const float2*>(&Xs[aRow[mt][1] + on]);
                }
            }
            #pragma unroll
            for (int nt = 0; nt < 8; ++nt)
                Bf[nt] = *reinterpret_cast<const float2*>(&Ws[bRow[nt] + o]);

            #pragma unroll
            for (int mt = 0; mt < 2; ++mt) {
                uint32_t a0 = __float_as_uint(Af[s][mt][0].x);
                uint32_t a1 = __float_as_uint(Af[s][mt][1].x);
                uint32_t a2 = __float_as_uint(Af[s][mt][0].y);
                uint32_t a3 = __float_as_uint(Af[s][mt][1].y);
                #pragma unroll
                for (int nt = 0; nt < 8; ++nt)
                    mma_tf32(acc[mt][nt], a0, a1, a2, a3,
                             __float_as_uint(Bf[nt].x), __float_as_uint(Bf[nt].y));
            }
        }
    }

    // ---- epilogue: out[t, e, o] ----
    #pragma unroll
    for (int mt = 0; mt < 2; ++mt) {
        const int t0 = tOff + mW + mt * 16 + g;
        float* p0 = out + ((size_t)t0 * EXPERTS + e) * OUTF + nOff + nW;
        float* p1 = p0 + (size_t)8 * EXPERTS * OUTF;
        #pragma unroll
        for (int nt = 0; nt < 8; ++nt) {
            int o = nt * 8 + 2 * tig;
            *reinterpret_cast<float2*>(p0 + o) = make_float2(acc[mt][nt][0], acc[mt][nt][1]);
            *reinterpret_cast<float2*>(p1 + o) = make_float2(acc[mt][nt][2], acc[mt][nt][3]);
        }
    }
}

extern "C" void kernel_launch(void* const* d_in, const int* in_sizes, int n_in,
                              void* d_out, int out_size)
{
    const float* x = (const float*)d_in[0];
    const float* W = (const float*)d_in[1];
    float* out = (float*)d_out;

    const int T = in_sizes[0] / (EXPERTS * RANK);

    const int nx4 = in_sizes[0] / 4;
    const int nw4 = in_sizes[1] / 4;
    round_x<<<(nx4 + 1023) / 1024, 1024>>>((const float4*)x, nx4);
    round_w<<<(nw4 + 1023) / 1024, 1024>>>((const float4*)W, nw4);

    cudaFuncSetAttribute(moelb_v7,
                         cudaFuncAttributeMaxDynamicSharedMemorySize, SMEM_TOTAL);

    dim3 grid(T / BM, OUTF / BN, EXPERTS);
    moelb_v7<<<grid, NTHREADS, SMEM_TOTAL>>>(out);
}

// round 11
// speedup vs baseline: 1.1262x; 1.1262x over previous
#include <cuda_runtime.h>
#include <cstdint>
#include <cstddef>

// out[t,e,o] = sum_r x[t, e*128+r] * W[e,o,r]
// x: [8192, 1024] f32, W: [8, 4096, 128] f32, out: [8192, 8, 4096] f32
//
// mma.sync TF32 (tcgen05 unavailable: harness compiles via compute_103 PTX).
// Round 11 = Round 8 economics with a 96KB CTA (tile 128x64: X 64KB + W 32KB)
// so TWO CTAs co-reside per SM: one CTA's cp.async fill + epilogue overlap the
// other's mainloop (R8's 192KB tile serialized CTAs completely).
// 4 warps (2M x 2N) of 64x32; operands pre-rounded to TF32 in scratch;
// 2-stage cp.async k-pipeline; LDS.64 k-slot-permutation fragments
// (MMA k-slots (tig,tig+4) of step j read phys k {8j+2tig, 8j+2tig+1},
// conflict-free under swizzle col ^= 8*(row&7)).

#define EXPERTS 8
#define RANK    128
#define OUTF    4096
#define TOKENS  8192
#define BM      128
#define BN      64
#define NTHREADS 128

#define SM_X 0
#define SM_W 65536
#define SMEM_TOTAL (65536 + 32768)   // 96KB

__device__ float g_Xr[(size_t)TOKENS * EXPERTS * RANK];   // 32MB tf32-rounded x
__device__ float g_Wr[(size_t)EXPERTS * OUTF * RANK];     // 16MB tf32-rounded W

__device__ __forceinline__ uint32_t tf32u(float f) {
    uint32_t u;
    asm("cvt.rna.tf32.f32 %0, %1;" : "=r"(u) : "f"(f));
    return u;
}
__device__ __forceinline__ uint32_t smem_u32(const void* p) {
    uint32_t a;
    asm("{ .reg .u64 t; cvta.to.shared.u64 t, %1; cvt.u32.u64 %0, t; }" : "=r"(a) : "l"(p));
    return a;
}
__device__ __forceinline__ void cp16(uint32_t dst, const void* src) {
    asm volatile("cp.async.cg.shared.global [%0], [%1], 16;" :: "r"(dst), "l"(src) : "memory");
}
__device__ __forceinline__ void mma_tf32(float c[4],
                                         uint32_t a0, uint32_t a1, uint32_t a2, uint32_t a3,
                                         uint32_t b0, uint32_t b1) {
    asm volatile(
        "mma.sync.aligned.m16n8k8.row.col.f32.tf32.tf32.f32 "
        "{%0,%1,%2,%3}, {%4,%5,%6,%7}, {%8,%9}, {%0,%1,%2,%3};"
        : "+f"(c[0]), "+f"(c[1]), "+f"(c[2]), "+f"(c[3])
        : "r"(a0), "r"(a1), "r"(a2), "r"(a3), "r"(b0), "r"(b1));
}

// ---- streaming pre-round kernels ----
__global__ void __launch_bounds__(1024, 2) round_x(const float4* __restrict__ src, int n4) {
    int i = blockIdx.x * blockDim.x + threadIdx.x;
    if (i < n4) {
        float4 v = src[i];
        reinterpret_cast<uint4*>(g_Xr)[i] =
            make_uint4(tf32u(v.x), tf32u(v.y), tf32u(v.z), tf32u(v.w));
    }
}
__global__ void __launch_bounds__(1024, 2) round_w(const float4* __restrict__ src, int n4) {
    int i = blockIdx.x * blockDim.x + threadIdx.x;
    if (i < n4) {
        float4 v = src[i];
        reinterpret_cast<uint4*>(g_Wr)[i] =
            make_uint4(tf32u(v.x), tf32u(v.y), tf32u(v.z), tf32u(v.w));
    }
}

extern "C" __global__ void __launch_bounds__(NTHREADS, 2)
moelb_v8(float* __restrict__ out)
{
    extern __shared__ char smem[];
    const uint32_t sb = smem_u32(smem);
    float* Xs = reinterpret_cast<float*>(smem + SM_X);   // [128][128] swizzled
    float* Ws = reinterpret_cast<float*>(smem + SM_W);   // [64][128] swizzled

    const int tid  = threadIdx.x;
    const int wid  = tid >> 5;
    const int lane = tid & 31;
    const int g    = lane >> 2;
    const int tig  = lane & 3;

    const int tOff = blockIdx.x * BM;
    const int nOff = blockIdx.y * BN;
    const int e    = blockIdx.z;

    // ---- issue both k-stages with cp.async (stage s covers float4 slots q=s*16..s*16+15) ----
    const float* xsrc = g_Xr + (size_t)tOff * (EXPERTS * RANK) + e * RANK;
    const float* wsrc = g_Wr + ((size_t)e * OUTF + nOff) * RANK;

    #pragma unroll
    for (int s = 0; s < 2; ++s) {
        #pragma unroll
        for (int p = 0; p < 16; ++p) {                    // X: 128 rows x 16 q
            int idx = p * NTHREADS + tid;
            int row = idx >> 4, q = s * 16 + (idx & 15);
            uint32_t dst = sb + SM_X + (uint32_t)row * 512
                         + (((uint32_t)q * 16) ^ (((uint32_t)row & 7) << 5));
            cp16(dst, xsrc + (size_t)row * (EXPERTS * RANK) + q * 4);
        }
        #pragma unroll
        for (int p = 0; p < 8; ++p) {                     // W: 64 rows x 16 q
            int idx = p * NTHREADS + tid;
            int row = idx >> 4, q = s * 16 + (idx & 15);
            uint32_t dst = sb + SM_W + (uint32_t)row * 512
                         + (((uint32_t)q * 16) ^ (((uint32_t)row & 7) << 5));
            cp16(dst, wsrc + (size_t)row * RANK + q * 4);
        }
        asm volatile("cp.async.commit_group;" ::: "memory");
    }

    // ---- warp mapping: 4 warps = 2(M) x 2(N), warp tile 64x32 ----
    const int mW  = (wid >> 1) * 64;       // 0 or 64
    const int nW  = (wid & 1) * 32;        // 0 or 32
    const int skf = g << 3;
    const int t2  = tig << 1;

    int aRow[4][2], bRow[4];
    #pragma unroll
    for (int mt = 0; mt < 4; ++mt) {
        aRow[mt][0] = (mW + mt * 16 + g) * RANK;
        aRow[mt][1] = (mW + mt * 16 + 8 + g) * RANK;
    }
    #pragma unroll
    for (int nt = 0; nt < 4; ++nt)
        bRow[nt] = (nW + nt * 8 + g) * RANK;

    float acc[4][4][4];
    #pragma unroll
    for (int mt = 0; mt < 4; ++mt)
        #pragma unroll
        for (int nt = 0; nt < 4; ++nt)
            #pragma unroll
            for (int i = 0; i < 4; ++i)
                acc[mt][nt][i] = 0.0f;

    float2 Af[2][4][2];
    float2 Bf[2][4];

    #pragma unroll
    for (int half = 0; half < 2; ++half) {
        if (half == 0) asm volatile("cp.async.wait_group 1;" ::: "memory");
        else           asm volatile("cp.async.wait_group 0;" ::: "memory");
        __syncthreads();

        // prologue: fragments for first k-step of this half
        {
            const int o = (((half * 8) << 3) ^ skf) + t2;
            #pragma unroll
            for (int mt = 0; mt < 4; ++mt) {
                Af[0][mt][0] = *reinterpret_cast<const float2*>(&Xs[aRow[mt][0] + o]);
                Af[0][mt][1] = *reinterpret_cast<const float2*>(&Xs[aRow[mt][1] + o]);
            }
            #pragma unroll
            for (int nt = 0; nt < 4; ++nt)
                Bf[0][nt] = *reinterpret_cast<const float2*>(&Ws[bRow[nt] + o]);
        }

        #pragma unroll
        for (int jj = 0; jj < 8; ++jj) {
            const int s = jj & 1;
            if (jj < 7) {
                const int on = (((half * 8 + jj + 1) << 3) ^ skf) + t2;
                const int n = s ^ 1;
                #pragma unroll
                for (int mt = 0; mt < 4; ++mt) {
                    Af[n][mt][0] = *reinterpret_cast<const float2*>(&Xs[aRow[mt][0] + on]);
                    Af[n][mt][1] = *reinterpret_cast<const float2*>(&Xs[aRow[mt][1] + on]);
                }
                #pragma unroll
                for (int nt = 0; nt < 4; ++nt)
                    Bf[n][nt] = *reinterpret_cast<const float2*>(&Ws[bRow[nt] + on]);
            }
            #pragma unroll
            for (int mt = 0; mt < 4; ++mt) {
                uint32_t a0 = __float_as_uint(Af[s][mt][0].x);
                uint32_t a1 = __float_as_uint(Af[s][mt][1].x);
                uint32_t a2 = __float_as_uint(Af[s][mt][0].y);
                uint32_t a3 = __float_as_uint(Af[s][mt][1].y);
                #pragma unroll
                for (int nt = 0; nt < 4; ++nt)
                    mma_tf32(acc[mt][nt], a0, a1, a2, a3,
                             __float_as_uint(Bf[s][nt].x), __float_as_uint(Bf[s][nt].y));
            }
        }
    }

    // ---- epilogue: out[t, e, o] ----
    #pragma unroll
    for (int mt = 0; mt < 4; ++mt) {
        const int t0 = tOff + mW + mt * 16 + g;
        float* p0 = out + ((size_t)t0 * EXPERTS + e) * OUTF + nOff + nW;
        float* p1 = p0 + (size_t)8 * EXPERTS * OUTF;
        #pragma unroll
        for (int nt = 0; nt < 4; ++nt) {
            int o = nt * 8 + 2 * tig;
            *reinterpret_cast<float2*>(p0 + o) = make_float2(acc[mt][nt][0], acc[mt][nt][1]);
            *reinterpret_cast<float2*>(p1 + o) = make_float2(acc[mt][nt][2], acc[mt][nt][3]);
        }
    }
}

extern "C" void kernel_launch(void* const* d_in, const int* in_sizes, int n_in,
                              void* d_out, int out_size)
{
    const float* x = (const float*)d_in[0];
    const float* W = (const float*)d_in[1];
    float* out = (float*)d_out;

    const int T = in_sizes[0] / (EXPERTS * RANK);

    const int nx4 = in_sizes[0] / 4;
    const int nw4 = in_sizes[1] / 4;
    round_x<<<(nx4 + 1023) / 1024, 1024>>>((const float4*)x, nx4);
    round_w<<<(nw4 + 1023) / 1024, 1024>>>((const float4*)W, nw4);

    cudaFuncSetAttribute(moelb_v8,
                         cudaFuncAttributeMaxDynamicSharedMemorySize, SMEM_TOTAL);

    dim3 grid(T / BM, OUTF / BN, EXPERTS);
    moelb_v8<<<grid, NTHREADS, SMEM_TOTAL>>>(out);
}